// round 15
// baseline (speedup 1.0000x reference)
#include <cuda_runtime.h>
#include <cuda_bf16.h>
#include <cstdint>

#define B 64
#define T 512
#define D 1024
#define H 1024
#define G 4096      // 4*H
#define PBLOCKS 128 // persistent grid size (<=148 SMs -> co-resident)

// ---------------- device scratch (no allocations allowed) ----------------
__device__ float g_Zpre[(size_t)T * B * G];        // [t][b][4H] pre-activations
__device__ float g_h[2][B * H];                    // ping-pong hidden state (fp32)
__device__ float g_c[B * H];                       // cell state
// packed bf16x2 planes for the input GEMM:
__device__ unsigned g_Apack[2][(size_t)B * T * 512];   // 134 MB
__device__ unsigned g_Wpack[2][(size_t)G * 512];       // 16 MB
// packed operands for the recurrence (validated layout):
__device__ uint4 g_hsplit[2][64 * B * 4];
__device__ uint4 g_Wsplit[64 * G * 4];                 // 16 MB
// distributed grid-barrier flags: one 128B-padded word per block
__device__ int g_flags[PBLOCKS * 32];

// ---------------- helpers ----------------
__device__ __forceinline__ void split_bf(float v, unsigned short& h, unsigned short& l) {
    __nv_bfloat16 hb = __float2bfloat16_rn(v);
    float r = v - __bfloat162float(hb);
    __nv_bfloat16 lb = __float2bfloat16_rn(r);
    h = *(unsigned short*)&hb;
    l = *(unsigned short*)&lb;
}

__device__ __forceinline__ unsigned pack2(unsigned short a, unsigned short b) {
    return (unsigned)a | ((unsigned)b << 16);
}

__device__ __forceinline__ void mma_bf16(float c[4], const unsigned a[4], const unsigned b[2]) {
    asm volatile(
        "mma.sync.aligned.m16n8k16.row.col.f32.bf16.bf16.f32 "
        "{%0,%1,%2,%3}, {%4,%5,%6,%7}, {%8,%9}, {%0,%1,%2,%3};"
        : "+f"(c[0]), "+f"(c[1]), "+f"(c[2]), "+f"(c[3])
        : "r"(a[0]), "r"(a[1]), "r"(a[2]), "r"(a[3]), "r"(b[0]), "r"(b[1]));
}

__device__ __forceinline__ float sigf(float x) {
    return 1.0f / (1.0f + __expf(-x));
}

__device__ __forceinline__ int read_len(const int* p, int b) {
    int is64 = (p[1] == 0);
    return is64 ? p[2 * b] : p[b];
}

// Distributed flag barrier: release own flag, acquire-poll all 128 flags
// (monotonic value t+1 -> no phase wraparound hazard; flags zeroed per layer).
__device__ __forceinline__ void barrier_step(int bid, int tid, int t) {
    __syncthreads();                       // CTA-order all h/state stores before release
    if (tid == 0) {
        asm volatile("st.release.gpu.global.s32 [%0], %1;"
                     :: "l"(g_flags + bid * 32), "r"(t + 1) : "memory");
    }
    if (tid < PBLOCKS) {
        const int* p = g_flags + tid * 32;
        int v;
        do {
            asm volatile("ld.acquire.gpu.global.s32 %0, [%1];"
                         : "=r"(v) : "l"(p) : "memory");
        } while (v < t + 1);
    }
    __syncthreads();                       // everyone inherits pollers' acquire
}

// ---------------- init ----------------
__global__ void init_state() {
    int i = blockIdx.x * 256 + threadIdx.x;
    if (i < B * H) { g_h[0][i] = 0.0f; g_c[i] = 0.0f; }
    if (i < 64 * B * 4) g_hsplit[0][i] = make_uint4(0, 0, 0, 0);
    if (i < PBLOCKS * 32) g_flags[i] = 0;
}

// ---------------- pre-split x into Apack ----------------
__global__ void split_x(const float* __restrict__ x) {
    size_t idx = (size_t)blockIdx.x * 256 + threadIdx.x;   // over B*T*512
    int kp = (int)(idx & 511);
    size_t r = idx >> 9;
    int b = (int)(r & 63);
    int t = (int)(r >> 6);
    float2 v = *(const float2*)(x + ((size_t)b * T + t) * D + 2 * kp);
    unsigned short h0, l0, h1, l1;
    split_bf(v.x, h0, l0);
    split_bf(v.y, h1, l1);
    g_Apack[0][idx] = pack2(h0, h1);
    g_Apack[1][idx] = pack2(l0, l1);
}

// ---------------- pre-split input-part of W into Wpack ----------------
__global__ void split_Win(const float* __restrict__ W) {
    size_t idx = (size_t)blockIdx.x * 256 + threadIdx.x;   // over G*512
    int col = (int)(idx & 4095);
    int kp = (int)(idx >> 12);
    float v0 = W[(size_t)(2 * kp) * G + col];
    float v1 = W[(size_t)(2 * kp + 1) * G + col];
    unsigned short h0, l0, h1, l1;
    split_bf(v0, h0, l0);
    split_bf(v1, h1, l1);
    g_Wpack[0][(size_t)col * 512 + kp] = pack2(h0, h1);
    g_Wpack[1][(size_t)col * 512 + kp] = pack2(l0, l1);
}

// ---------------- pre-split recurrent Wh (validated layout) ----------------
__global__ void split_W(const float* __restrict__ Wh) {
    int idx = blockIdx.x * 256 + threadIdx.x;   // 0 .. 64*4096*4-1
    int tg = idx & 3;
    int gcol = (idx >> 2) & 4095;
    int kg = idx >> 14;
    int k0 = 16 * kg + 2 * tg;
    float v00 = Wh[(size_t)(k0) * G + gcol];
    float v01 = Wh[(size_t)(k0 + 1) * G + gcol];
    float v10 = Wh[(size_t)(k0 + 8) * G + gcol];
    float v11 = Wh[(size_t)(k0 + 9) * G + gcol];
    unsigned short h00, l00, h01, l01, h10, l10, h11, l11;
    split_bf(v00, h00, l00);
    split_bf(v01, h01, l01);
    split_bf(v10, h10, l10);
    split_bf(v11, h11, l11);
    g_Wsplit[idx] = make_uint4(pack2(h00, h01), pack2(h10, h11),
                               pack2(l00, l01), pack2(l10, l11));
}

// ---------------- input GEMM, 3xBF16 (validated round 11) ----------------
__global__ __launch_bounds__(256) void gemm_in(const float* __restrict__ bias) {
    __shared__ unsigned As[2][128][20];
    __shared__ unsigned Bs[2][128][20];

    const int bm = blockIdx.y, bn = blockIdx.x;
    const int tid = threadIdx.x;
    const int wid = tid >> 5, lane = tid & 31;
    const int wm = wid & 3, wn = wid >> 2;
    const int gq = lane >> 2, tg = lane & 3;

    const int l_row = tid >> 2;
    const int l_kp4 = (tid & 3) << 2;

    const unsigned* Ap[2] = {g_Apack[0] + (size_t)(bm * 128) * 512,
                             g_Apack[1] + (size_t)(bm * 128) * 512};
    const unsigned* Wp[2] = {g_Wpack[0] + (size_t)(bn * 128) * 512,
                             g_Wpack[1] + (size_t)(bn * 128) * 512};

    float acc[2][8][4];
#pragma unroll
    for (int mt = 0; mt < 2; mt++)
#pragma unroll
        for (int nt = 0; nt < 8; nt++)
#pragma unroll
            for (int q = 0; q < 4; q++) acc[mt][nt][q] = 0.0f;

    uint4 pa[2][2], pb[2][2];
#pragma unroll
    for (int pl = 0; pl < 2; pl++)
#pragma unroll
        for (int i = 0; i < 2; i++) {
            pa[pl][i] = *(const uint4*)(Ap[pl] + (size_t)(l_row + i * 64) * 512 + l_kp4);
            pb[pl][i] = *(const uint4*)(Wp[pl] + (size_t)(l_row + i * 64) * 512 + l_kp4);
        }

    for (int c = 0; c < 32; c++) {
#pragma unroll
        for (int pl = 0; pl < 2; pl++)
#pragma unroll
            for (int i = 0; i < 2; i++) {
                *(uint4*)&As[pl][l_row + i * 64][l_kp4] = pa[pl][i];
                *(uint4*)&Bs[pl][l_row + i * 64][l_kp4] = pb[pl][i];
            }
        __syncthreads();
        if (c < 31) {
            int kb = (c + 1) * 16 + l_kp4;
#pragma unroll
            for (int pl = 0; pl < 2; pl++)
#pragma unroll
                for (int i = 0; i < 2; i++) {
                    pa[pl][i] = *(const uint4*)(Ap[pl] + (size_t)(l_row + i * 64) * 512 + kb);
                    pb[pl][i] = *(const uint4*)(Wp[pl] + (size_t)(l_row + i * 64) * 512 + kb);
                }
        }
#pragma unroll
        for (int ks = 0; ks < 2; ks++) {
            unsigned ah[2][4], al[2][4];
#pragma unroll
            for (int mt = 0; mt < 2; mt++) {
                int row = wm * 32 + mt * 16;
                int cc = ks * 8;
                ah[mt][0] = As[0][row + gq][cc + tg];
                ah[mt][1] = As[0][row + gq + 8][cc + tg];
                ah[mt][2] = As[0][row + gq][cc + tg + 4];
                ah[mt][3] = As[0][row + gq + 8][cc + tg + 4];
                al[mt][0] = As[1][row + gq][cc + tg];
                al[mt][1] = As[1][row + gq + 8][cc + tg];
                al[mt][2] = As[1][row + gq][cc + tg + 4];
                al[mt][3] = As[1][row + gq + 8][cc + tg + 4];
            }
#pragma unroll
            for (int nt = 0; nt < 8; nt++) {
                int col = wn * 64 + nt * 8 + gq;
                unsigned bh[2], bl[2];
                bh[0] = Bs[0][col][ks * 8 + tg];
                bh[1] = Bs[0][col][ks * 8 + tg + 4];
                bl[0] = Bs[1][col][ks * 8 + tg];
                bl[1] = Bs[1][col][ks * 8 + tg + 4];
#pragma unroll
                for (int mt = 0; mt < 2; mt++) {
                    mma_bf16(acc[mt][nt], ah[mt], bh);
                    mma_bf16(acc[mt][nt], ah[mt], bl);
                    mma_bf16(acc[mt][nt], al[mt], bh);
                }
            }
        }
        __syncthreads();
    }

#pragma unroll
    for (int mt = 0; mt < 2; mt++) {
#pragma unroll
        for (int nt = 0; nt < 8; nt++) {
            int row = bm * 128 + wm * 32 + mt * 16 + gq;
            int col = bn * 128 + wn * 64 + nt * 8 + tg * 2;
            float b0v = bias[col], b1v = bias[col + 1];
            g_Zpre[(size_t)row * G + col]     = acc[mt][nt][0] + b0v;
            g_Zpre[(size_t)row * G + col + 1] = acc[mt][nt][1] + b1v;
            g_Zpre[(size_t)(row + 8) * G + col]     = acc[mt][nt][2] + b0v;
            g_Zpre[(size_t)(row + 8) * G + col + 1] = acc[mt][nt][3] + b1v;
        }
    }
}

// ---------------- persistent recurrence, 3xBF16, zero-duplication tiling ----------------
// 128 blocks x 256 threads (8 warps). Block owns 8 hidden units (32 gate cols).
// Warp w = K-slice kg in [8w, 8w+8); warp tile M=64 (4 m-tiles) x N=32 (4 n-tiles).
// Distributed flag barrier between steps.
#define ZS_STRIDE 36
__global__ __launch_bounds__(256) void lstm_persist(const int* __restrict__ lens,
                                                    int ymode,
                                                    float* __restrict__ yout) {
    extern __shared__ float Zsd[];    // [8][64][ZS_STRIDE] partial z tiles
    __shared__ int Ls[64];

    const int tid = threadIdx.x;
    const int wid = tid >> 5;
    const int lane = tid & 31;
    const int gq = lane >> 2, tg = lane & 3;
    const int bid = blockIdx.x;
    const int n0 = bid * 8;
    const int kgbase = wid * 8;

    if (tid < 64) Ls[tid] = read_len(lens, tid);
    __syncthreads();

    // per-lane fragment offsets
    int aoff[4][2];
#pragma unroll
    for (int mt = 0; mt < 4; mt++) {
        aoff[mt][0] = (16 * mt + gq) * 4 + tg;        // + kg*256
        aoff[mt][1] = (16 * mt + gq + 8) * 4 + tg;
    }
    int gcol[4];
#pragma unroll
    for (int nt = 0; nt < 4; nt++)
        gcol[nt] = (nt * H + n0 + gq) * 4 + tg;       // + kg*16384

    for (int t = 0; t < T; t++) {
        const float* __restrict__ h_in  = g_h[t & 1];
        float* __restrict__ h_out = g_h[(t + 1) & 1];
        const uint4* __restrict__ Ah = g_hsplit[t & 1];
        uint4* __restrict__ Aout = g_hsplit[(t + 1) & 1];
        const float* __restrict__ Zpre_t = g_Zpre + (size_t)t * B * G;

        float acc[4][4][4];
#pragma unroll
        for (int mt = 0; mt < 4; mt++)
#pragma unroll
            for (int nt = 0; nt < 4; nt++)
#pragma unroll
                for (int q = 0; q < 4; q++) acc[mt][nt][q] = 0.0f;

        uint4 av[4][2], wv[4];
        {
            const uint4* Ak = Ah + kgbase * 256;
#pragma unroll
            for (int mt = 0; mt < 4; mt++) {
                av[mt][0] = __ldcg(Ak + aoff[mt][0]);
                av[mt][1] = __ldcg(Ak + aoff[mt][1]);
            }
            const uint4* Wk = g_Wsplit + kgbase * 16384;
#pragma unroll
            for (int nt = 0; nt < 4; nt++) wv[nt] = __ldg(Wk + gcol[nt]);
        }

#pragma unroll
        for (int kg2 = 0; kg2 < 8; kg2++) {
            uint4 nav[4][2], nwv[4];
            if (kg2 < 7) {
                const int kg = kgbase + kg2 + 1;
                const uint4* Ak = Ah + kg * 256;
#pragma unroll
                for (int mt = 0; mt < 4; mt++) {
                    nav[mt][0] = __ldcg(Ak + aoff[mt][0]);
                    nav[mt][1] = __ldcg(Ak + aoff[mt][1]);
                }
                const uint4* Wk = g_Wsplit + kg * 16384;
#pragma unroll
                for (int nt = 0; nt < 4; nt++) nwv[nt] = __ldg(Wk + gcol[nt]);
            }
#pragma unroll
            for (int nt = 0; nt < 4; nt++) {
                unsigned bh[2] = {wv[nt].x, wv[nt].y};
                unsigned bl[2] = {wv[nt].z, wv[nt].w};
#pragma unroll
                for (int mt = 0; mt < 4; mt++) {
                    unsigned ah[4] = {av[mt][0].x, av[mt][1].x, av[mt][0].y, av[mt][1].y};
                    unsigned al[4] = {av[mt][0].z, av[mt][1].z, av[mt][0].w, av[mt][1].w};
                    mma_bf16(acc[mt][nt], ah, bh);
                    mma_bf16(acc[mt][nt], ah, bl);
                    mma_bf16(acc[mt][nt], al, bh);
                }
            }
#pragma unroll
            for (int mt = 0; mt < 4; mt++) { av[mt][0] = nav[mt][0]; av[mt][1] = nav[mt][1]; }
#pragma unroll
            for (int nt = 0; nt < 4; nt++) wv[nt] = nwv[nt];
        }

        // store partial z tile for this warp's K-slice
        float* Zw = Zsd + (size_t)wid * 64 * ZS_STRIDE;
#pragma unroll
        for (int mt = 0; mt < 4; mt++) {
#pragma unroll
            for (int nt = 0; nt < 4; nt++) {
                int row = 16 * mt + gq;
                int col = nt * 8 + tg * 2;
                Zw[row * ZS_STRIDE + col]     = acc[mt][nt][0];
                Zw[row * ZS_STRIDE + col + 1] = acc[mt][nt][1];
                Zw[(row + 8) * ZS_STRIDE + col]     = acc[mt][nt][2];
                Zw[(row + 8) * ZS_STRIDE + col + 1] = acc[mt][nt][3];
            }
        }
        __syncthreads();

        // fused gates + masking; 64 batch x 8 units = 512 items, 2 per thread
#pragma unroll
        for (int p = 0; p < 2; p++) {
            int it = tid + p * 256;
            int b = it >> 3;
            int nn = it & 7;
            int n = n0 + nn;
            size_t zb = (size_t)b * G;
            float zi = Zpre_t[zb + 0 * H + n];
            float zj = Zpre_t[zb + 1 * H + n];
            float zf = Zpre_t[zb + 2 * H + n];
            float zo = Zpre_t[zb + 3 * H + n];
#pragma unroll
            for (int w = 0; w < 8; w++) {
                const float* Zw = Zsd + ((size_t)w * 64 + b) * ZS_STRIDE;
                zi += Zw[0 * 8 + nn];
                zj += Zw[1 * 8 + nn];
                zf += Zw[2 * 8 + nn];
                zo += Zw[3 * 8 + nn];
            }
            size_t hi = (size_t)b * H + n;
            bool m = t < Ls[b];
            float yv = 0.0f;
            float newh;
            if (m) {
                float cv = g_c[hi];
                float cn = cv * sigf(zf + 1.0f) + sigf(zi) * tanhf(zj);
                newh = tanhf(cn) * sigf(zo);
                g_c[hi] = cn;
                yv = newh;
            } else {
                newh = __ldcg(h_in + hi);
            }
            h_out[hi] = newh;
            // packed bf16 split write of newh for next step's A-fragments
            {
                int kg = n >> 4;
                int k15 = n & 15;
                int tg2 = (k15 & 7) >> 1;
                int cbit = k15 & 1;
                int w = k15 >> 3;
                unsigned short hu, lu;
                split_bf(newh, hu, lu);
                unsigned short* base = (unsigned short*)(Aout + (kg * 64 + b) * 4 + tg2);
                base[w * 2 + cbit]     = hu;
                base[4 + w * 2 + cbit] = lu;
            }
            if (ymode == 0) {
                size_t r = (size_t)t * B + b;
                unsigned short hu, lu;
                split_bf(yv, hu, lu);
                ((unsigned short*)(g_Apack[0] + r * 512 + (n >> 1)))[n & 1] = hu;
                ((unsigned short*)(g_Apack[1] + r * 512 + (n >> 1)))[n & 1] = lu;
            } else {
                yout[((size_t)b * T + t) * H + n] = yv;
            }
        }

        barrier_step(bid, tid, t);
    }
}

// ---------------- final h/c copy ----------------
__global__ void copy_hc(float* __restrict__ out_h, float* __restrict__ out_c) {
    int i = blockIdx.x * 256 + threadIdx.x;
    if (i < B * H) { out_h[i] = g_h[0][i]; out_c[i] = g_c[i]; }
}

// ---------------- launch ----------------
extern "C" void kernel_launch(void* const* d_in, const int* in_sizes, int n_in,
                              void* d_out, int out_size) {
    const float* x = nullptr;
    const int* lengths = nullptr;
    const float* W0 = nullptr; const float* b0 = nullptr;
    const float* W1 = nullptr; const float* b1 = nullptr;
    int wseen = 0, bseen = 0;
    for (int i = 0; i < n_in; i++) {
        long long s = in_sizes[i];
        if (s == (long long)B * T * D) x = (const float*)d_in[i];
        else if (s == B) lengths = (const int*)d_in[i];
        else if (s == (long long)(D + H) * G) {
            if (wseen++ == 0) W0 = (const float*)d_in[i];
            else W1 = (const float*)d_in[i];
        } else if (s == G) {
            if (bseen++ == 0) b0 = (const float*)d_in[i];
            else b1 = (const float*)d_in[i];
        }
    }

    float* out = (float*)d_out;
    float* out_y = out;
    float* out_h = out + (size_t)B * T * H;      // h_stack [2][B][H]
    float* out_c = out_h + 2 * B * H;            // c_stack [2][B][H]

    const size_t zs_bytes = 8 * 64 * ZS_STRIDE * sizeof(float);   // 73728
    cudaFuncSetAttribute(lstm_persist, cudaFuncAttributeMaxDynamicSharedMemorySize,
                         (int)zs_bytes);

    const int sgrid = (B * H + 255) / 256;
    dim3 ggrid(G / 128, (B * T) / 128);          // 32 x 256
    const int wgrid = (64 * G * 4) / 256;
    const int xgrid = (B * T * 512) / 256;       // 65536
    const int wingrid = (G * 512) / 256;         // 8192

    // ---- layer 0 ----
    init_state<<<sgrid, 256>>>();
    split_x<<<xgrid, 256>>>(x);
    split_Win<<<wingrid, 256>>>(W0);
    split_W<<<wgrid, 256>>>(W0 + (size_t)D * G);
    gemm_in<<<ggrid, 256>>>(b0);
    lstm_persist<<<PBLOCKS, 256, zs_bytes>>>(lengths, 0, nullptr);
    copy_hc<<<sgrid, 256>>>(out_h, out_c);

    // ---- layer 1 ----
    init_state<<<sgrid, 256>>>();
    split_Win<<<wingrid, 256>>>(W1);
    split_W<<<wgrid, 256>>>(W1 + (size_t)H * G);
    gemm_in<<<ggrid, 256>>>(b1);
    lstm_persist<<<PBLOCKS, 256, zs_bytes>>>(lengths, 1, out_y);
    copy_hc<<<sgrid, 256>>>(out_h + B * H, out_c + B * H);
}